// round 9
// baseline (speedup 1.0000x reference)
#include <cuda_runtime.h>
#include <cstdint>

// Problem constants
#define BB 4
#define SS 8192
#define DD 64
#define NH 8
#define NB 128   // n_buckets

#define OUT_ELEMS  (BB * SS * DD)   // 2,097,152
#define BKT_ELEMS  (BB * NH * SS)   // 262,144

#define TPB     64    // tokens per block
#define THREADS 256   // 4 h-groups x 64 threads
#define NBLK    ((BB * SS) / TPB)   // 512 blocks
#define QS      68    // qT row stride (mult of 4; 4-way stage conflicts only)

#define SMEM_QT_FLOATS (64 * QS)       // 4352
#define SMEM_RS_FLOATS (4 * 64 * 64)   // 16384 (4 h slices at a time)
#define SMEM_BYTES ((SMEM_QT_FLOATS + SMEM_RS_FLOATS) * 4)   // 82,944 B

__device__ __forceinline__ unsigned long long pack2(float x) {
    unsigned long long r;
    asm("mov.b64 %0, {%1, %1};" : "=l"(r) : "f"(x));
    return r;
}
__device__ __forceinline__ void fma2(unsigned long long& a,
                                     unsigned long long x,
                                     unsigned long long y) {
    asm("fma.rn.f32x2 %0, %1, %2, %0;" : "+l"(a) : "l"(x), "l"(y));
}
__device__ __forceinline__ float lo32(unsigned long long a) {
    return __uint_as_float((unsigned)(a & 0xffffffffull));
}
__device__ __forceinline__ float hi32(unsigned long long a) {
    return __uint_as_float((unsigned)(a >> 32));
}

// ---------------------------------------------------------------------------
// Fused kernel:
//   (a) out[0:OUT] = v   (the masked LSH attention collapses to an exact copy)
//   (b) out_b[b, h*S + t] = argmax_i concat(r, -r) + h*NB,
//       r[i] = sum_d qk[b,t,d] * rot[d, h, i]
//
// 512 CTAs x 256 threads. Each CTA owns 64 tokens. Threads split into 4
// h-groups (hg = tid>>6) of 64 threads; within a group: part = 8 i's,
// tg = 8 tokens. Each thread processes 2 hashes (h = hg*2 + j, j=0..1).
// This quadruples resident warps (2 CTAs/SM via launch_bounds -> 16 warps/SM)
// while keeping the 8tok x 8i tile that balances LDS bytes vs FFMA2.
// ---------------------------------------------------------------------------
__global__ void __launch_bounds__(THREADS, 2)
lsh_fused_kernel(const float* __restrict__ qk,
                 const float* __restrict__ rot,
                 const float* __restrict__ v,
                 float* __restrict__ out,
                 float* __restrict__ out_b,
                 int do_copy, int do_bkt) {
    extern __shared__ float sm[];
    float* qT = sm;                    // [d][t_local], stride QS
    float* rs = sm + SMEM_QT_FLOATS;   // [hg][d][i], 4 slices of 64x64

    const int tid   = threadIdx.x;
    const int g0    = blockIdx.x * TPB;
    const int b     = g0 >> 13;            // g0 / SS
    const int tbase = g0 & (SS - 1);

    // (a) copy this block's v slice (hides under compute)
    if (do_copy) {
        const float4* vs = (const float4*)v + (size_t)g0 * (DD / 4);
        float4*       os = (float4*)out    + (size_t)g0 * (DD / 4);
        #pragma unroll
        for (int e = tid; e < TPB * DD / 4; e += THREADS) os[e] = vs[e];
    }
    if (!do_bkt) return;

    // stage q transposed (coalesced global; 4-way smem store conflicts, tiny)
    for (int e = tid; e < TPB * 64; e += THREADS) {
        int tl = e & (TPB - 1), d = e >> 6;   // e = d*64 + tl
        qT[d * QS + tl] = qk[(size_t)(g0 + tl) * DD + d];
    }

    const int hg   = tid >> 6;          // h-group 0..3
    const int t6   = tid & 63;
    const int part = t6 & 7;            // i in [part*8, part*8+8)
    const int tg   = t6 >> 3;           // tokens tg*8 .. tg*8+7
    const float* qp = qT + tg * 8;
    const float* rp = rs + hg * 4096 + part * 8;
    const int i0 = part * 8;

    #pragma unroll
    for (int j = 0; j < 2; ++j) {
        const int h = hg * 2 + j;
        __syncthreads();   // also covers qT readiness on j==0
        // stage 4 rot slices: rs[hg'][d][i] = rot[d, hg'*2+j, i] (coalesced)
        for (int e = tid; e < 4 * 64 * 64; e += THREADS) {
            int hgs = e >> 12, d = (e >> 6) & 63, i = e & 63;
            rs[e] = rot[d * (NH * 64) + (hgs * 2 + j) * 64 + i];
        }
        __syncthreads();

        unsigned long long acc[4][8];   // [token-pair][i]
        #pragma unroll
        for (int p = 0; p < 4; ++p)
            #pragma unroll
            for (int k = 0; k < 8; ++k) acc[p][k] = 0ull;

        #pragma unroll 4
        for (int d = 0; d < 64; ++d) {
            ulonglong2 qA = *(const ulonglong2*)(qp + d * QS);
            ulonglong2 qB = *(const ulonglong2*)(qp + d * QS + 4);
            float4 r0 = *(const float4*)(rp + d * 64);
            float4 r1 = *(const float4*)(rp + d * 64 + 4);
            unsigned long long qq[4] = {qA.x, qA.y, qB.x, qB.y};
            unsigned long long rr[8] = {
                pack2(r0.x), pack2(r0.y), pack2(r0.z), pack2(r0.w),
                pack2(r1.x), pack2(r1.y), pack2(r1.z), pack2(r1.w)};
            #pragma unroll
            for (int p = 0; p < 4; ++p)
                #pragma unroll
                for (int k = 0; k < 8; ++k)
                    fma2(acc[p][k], qq[p], rr[k]);
        }

        // per-token argmax over [r, -r]; strict '>' = first-occurrence ties
        #pragma unroll
        for (int p = 0; p < 4; ++p) {
            #pragma unroll
            for (int half = 0; half < 2; ++half) {
                float vv[8];
                #pragma unroll
                for (int k = 0; k < 8; ++k)
                    vv[k] = half ? hi32(acc[p][k]) : lo32(acc[p][k]);

                float bv = vv[0]; int bi = i0;
                #pragma unroll
                for (int k = 1; k < 8; ++k)
                    if (vv[k] > bv) { bv = vv[k]; bi = i0 + k; }
                #pragma unroll
                for (int k = 0; k < 8; ++k) {
                    float nv = -vv[k];
                    if (nv > bv) { bv = nv; bi = 64 + i0 + k; }
                }
                // reduce across 8 parts (consecutive lanes)
                #pragma unroll
                for (int off = 4; off >= 1; off >>= 1) {
                    float ov = __shfl_down_sync(0xFFFFFFFFu, bv, off);
                    int   oi = __shfl_down_sync(0xFFFFFFFFu, bi, off);
                    if (ov > bv || (ov == bv && oi < bi)) { bv = ov; bi = oi; }
                }
                if (part == 0) {
                    int t = tbase + tg * 8 + p * 2 + half;
                    out_b[(size_t)b * (NH * SS) + (size_t)h * SS + t] =
                        (float)(bi + h * NB);
                }
            }
        }
    }
}

extern "C" void kernel_launch(void* const* d_in, const int* in_sizes, int n_in,
                              void* d_out, int out_size) {
    const float* qk  = (const float*)d_in[0];
    const float* v   = (const float*)d_in[1];
    const float* rot = (const float*)d_in[2];
    float* out = (float*)d_out;

    cudaFuncSetAttribute(lsh_fused_kernel,
                         cudaFuncAttributeMaxDynamicSharedMemorySize,
                         SMEM_BYTES);

    int do_copy = (out_size >= OUT_ELEMS) ? 1 : 0;
    int do_bkt  = (out_size == OUT_ELEMS + BKT_ELEMS || out_size == BKT_ELEMS) ? 1 : 0;
    float* out_b = (out_size == BKT_ELEMS) ? out : out + OUT_ELEMS;

    lsh_fused_kernel<<<NBLK, THREADS, SMEM_BYTES>>>(
        qk, rot, v, out, out_b, do_copy, do_bkt);
}